// round 3
// baseline (speedup 1.0000x reference)
#include <cuda_runtime.h>
#include <cuda_bf16.h>
#include <cstdint>
#include <cstddef>

#define FULL 0xffffffffu
#define TILE 128
#define FS 44   // feats shared stride in floats -> conflict-free A-fragment LDS

// ---------------- static device scratch (no allocations allowed) ------------
static __device__ float g_e[4194304];       // per-cell exp(w)
static __device__ int   g_starts[65536];
static __device__ int   g_ends[65536];
static __device__ float g_impc[65536];
static __device__ float g_validf[65536];

// ---------------- helpers ---------------------------------------------------
__device__ __forceinline__ uint32_t f2tf32(float f) {
  uint32_t u;
  asm("cvt.rna.tf32.f32 %0, %1;" : "=r"(u) : "f"(f));
  return u;
}

__device__ __forceinline__ float wsum(float v) {
  v += __shfl_xor_sync(FULL, v, 16);
  v += __shfl_xor_sync(FULL, v, 8);
  v += __shfl_xor_sync(FULL, v, 4);
  v += __shfl_xor_sync(FULL, v, 2);
  v += __shfl_xor_sync(FULL, v, 1);
  return v;
}

// ---------------- K0: zero segment boundary arrays ---------------------------
__global__ void k_zero(int K) {
  int i = blockIdx.x * blockDim.x + threadIdx.x;
  if (i < K) { g_starts[i] = 0; g_ends[i] = 0; }
}

// ---------------- K0b: segment boundaries (seg_ids sorted) -------------------
__global__ void k_bounds(const int* __restrict__ seg, int N) {
  int i = blockIdx.x * blockDim.x + threadIdx.x;
  if (i >= N) return;
  int cur = seg[i];
  if (i == 0) g_starts[cur] = 0;
  int nxt = (i + 1 < N) ? seg[i + 1] : -1;
  if (nxt != cur) {
    g_ends[cur] = i + 1;
    if (i + 1 < N) g_starts[nxt] = i + 1;
  }
}

// ---------------- K1: per-cell MLP (tf32 MMA) -> e = exp(w) ------------------
// 256 threads = 8 warps; each warp owns one m16 tile (16 cells) -> 128/block.
// feats = [state(32) | arch(4) | zero pad(4)]  (k padded 36 -> 40 = 5 k-tiles)
__global__ void __launch_bounds__(256) k_cell(
    const float* __restrict__ state, const float* __restrict__ arch,
    const float* __restrict__ energy, const float* __restrict__ phil,
    const float* __restrict__ W1, const float* __restrict__ b1,
    const float* __restrict__ W2, const float* __restrict__ b2,
    int N)
{
  __shared__ float  feats[TILE * FS];   // 22.0 KB
  __shared__ uint2  bfrag[1280];        // 10.0 KB  [kt][nt][lane] tf32 B frags
  __shared__ float2 w2b1[64];           // {b1[col], W2[col]}
  __shared__ float  basebuf[TILE];

  int tid = threadIdx.x;
  int base = blockIdx.x * TILE;

  // ---- stage W1 as m16n8k8 .row.col B fragments:
  // b.x = B[k0][n], b.y = B[k0+4][n], k0 = kt*8+(lane&3), n = nt*8+(lane>>2)
  #pragma unroll
  for (int it = 0; it < 5; it++) {
    int idx = tid + it * 256;
    int l = idx & 31, nt = (idx >> 5) & 7, kt = idx >> 8;
    int k0 = kt * 8 + (l & 3), n = nt * 8 + (l >> 2);
    float f0 = (k0     < 36) ? W1[k0 * 64 + n]       : 0.f;
    float f1 = (k0 + 4 < 36) ? W1[(k0 + 4) * 64 + n] : 0.f;
    bfrag[idx] = make_uint2(f2tf32(f0), f2tf32(f1));
  }
  if (tid < 64) w2b1[tid] = make_float2(b1[tid], W2[tid]);

  // ---- stage feats (coalesced float4)
  const float4* st4 = (const float4*)state;
  const float4* ar4 = (const float4*)arch;
  float4 z4 = make_float4(0.f, 0.f, 0.f, 0.f);
  #pragma unroll
  for (int it = 0; it < 4; it++) {
    int j = tid + it * 256;
    int row = j >> 3, q = j & 7;
    int cell = base + row;
    float4 v = (cell < N) ? st4[(size_t)cell * 8 + q] : z4;
    *(float4*)&feats[row * FS + q * 4] = v;
  }
  if (tid < TILE) {
    int cell = base + tid;
    float4 a = (cell < N) ? ar4[cell] : z4;
    *(float4*)&feats[tid * FS + 32] = a;
    *(float4*)&feats[tid * FS + 36] = z4;   // k-pad 36..39
  }
  __syncthreads();

  int warp = tid >> 5, lane = tid & 31;
  int grp = lane >> 2, tig = lane & 3;
  int r0 = warp * 16 + grp;

  float acc[8][4];
  #pragma unroll
  for (int nt = 0; nt < 8; nt++) {
    acc[nt][0] = 0.f; acc[nt][1] = 0.f; acc[nt][2] = 0.f; acc[nt][3] = 0.f;
  }

  // ---- 5 k-tiles x 8 n-tiles of mma.m16n8k8.tf32
  #pragma unroll
  for (int kt = 0; kt < 5; kt++) {
    const float* fp = &feats[r0 * FS + kt * 8 + tig];
    uint32_t a0 = f2tf32(fp[0]);
    uint32_t a1 = f2tf32(fp[8 * FS]);
    uint32_t a2 = f2tf32(fp[4]);
    uint32_t a3 = f2tf32(fp[8 * FS + 4]);
    #pragma unroll
    for (int nt = 0; nt < 8; nt++) {
      uint2 b = bfrag[kt * 256 + nt * 32 + lane];
      asm volatile(
        "mma.sync.aligned.m16n8k8.row.col.f32.tf32.tf32.f32 "
        "{%0,%1,%2,%3}, {%4,%5,%6,%7}, {%8,%9}, {%0,%1,%2,%3};"
        : "+f"(acc[nt][0]), "+f"(acc[nt][1]), "+f"(acc[nt][2]), "+f"(acc[nt][3])
        : "r"(a0), "r"(a1), "r"(a2), "r"(a3), "r"(b.x), "r"(b.y));
    }
  }

  // ---- epilogue: base = sigmoid(relu(h+b1).W2 + b2), folded in registers
  // C frag: c0,c1 = row r0 cols {8nt+2tig, +1}; c2,c3 = row r0+8 same cols
  float p0 = 0.f, p1 = 0.f;
  #pragma unroll
  for (int nt = 0; nt < 8; nt++) {
    int col = nt * 8 + tig * 2;
    float2 u = w2b1[col], v = w2b1[col + 1];
    p0 += fmaxf(acc[nt][0] + u.x, 0.f) * u.y + fmaxf(acc[nt][1] + v.x, 0.f) * v.y;
    p1 += fmaxf(acc[nt][2] + u.x, 0.f) * u.y + fmaxf(acc[nt][3] + v.x, 0.f) * v.y;
  }
  p0 += __shfl_xor_sync(FULL, p0, 1);
  p0 += __shfl_xor_sync(FULL, p0, 2);
  p1 += __shfl_xor_sync(FULL, p1, 1);
  p1 += __shfl_xor_sync(FULL, p1, 2);
  if (tig == 0) {
    float B2 = *b2;
    basebuf[r0]     = 1.f / (1.f + __expf(-(p0 + B2)));
    basebuf[r0 + 8] = 1.f / (1.f + __expf(-(p1 + B2)));
  }
  __syncthreads();

  // ---- w = clip(base*e*p,.01,1)*e*p; store exp(w) (max shift dropped: w in [0,1])
  if (tid < TILE) {
    int cell = base + tid;
    if (cell < N) {
      float ep = energy[cell] * phil[cell];
      float imp = fminf(fmaxf(basebuf[tid] * ep, 0.01f), 1.f);
      g_e[cell] = __expf(imp * ep);
    }
  }
}

// ---------------- K2: one warp per cluster — reductions + cluster MLP --------
__global__ void k_cluster(
    const float* __restrict__ arch, const float* __restrict__ surprise,
    const float* __restrict__ V1, const float* __restrict__ c1,
    const float* __restrict__ V2, const float* __restrict__ c2,
    float* __restrict__ out, int K)
{
  int wid  = (blockIdx.x * blockDim.x + threadIdx.x) >> 5;
  int lane = threadIdx.x & 31;
  if (wid >= K) return;
  int s = g_starts[wid], e = g_ends[wid];
  const float4* ar4 = (const float4*)arch;

  float se = 0.f;
  float ea0 = 0.f, ea1 = 0.f, ea2 = 0.f, ea3 = 0.f;
  float sa0 = 0.f, sa1 = 0.f, sa2 = 0.f, sa3 = 0.f;
  float q0 = 0.f, q1 = 0.f, q2 = 0.f, q3 = 0.f;
  float ssur = 0.f;
  for (int i = s + lane; i < e; i += 32) {
    float4 a = ar4[i];
    float ev = g_e[i];
    float sp = surprise[i];
    se += ev;
    ea0 += ev * a.x; ea1 += ev * a.y; ea2 += ev * a.z; ea3 += ev * a.w;
    sa0 += a.x;      sa1 += a.y;      sa2 += a.z;      sa3 += a.w;
    q0 += a.x * a.x; q1 += a.y * a.y; q2 += a.z * a.z; q3 += a.w * a.w;
    ssur += sp;
  }
  se  = wsum(se);
  ea0 = wsum(ea0); ea1 = wsum(ea1); ea2 = wsum(ea2); ea3 = wsum(ea3);
  sa0 = wsum(sa0); sa1 = wsum(sa1); sa2 = wsum(sa2); sa3 = wsum(sa3);
  q0  = wsum(q0);  q1  = wsum(q1);  q2  = wsum(q2);  q3  = wsum(q3);
  ssur = wsum(ssur);

  int icnt = e - s;
  float counts = (float)icnt;
  bool  valid = icnt > 0;
  float cnt = fmaxf(counts, 1.f);

  // aggregate = softmax(segsum(wn*arch)); segsum(wn*arch) == ea/se (shift-free)
  float g0v = valid ? ea0 / se : 0.f;
  float g1v = valid ? ea1 / se : 0.f;
  float g2v = valid ? ea2 / se : 0.f;
  float g3v = valid ? ea3 / se : 0.f;
  float mx = fmaxf(fmaxf(g0v, g1v), fmaxf(g2v, g3v));
  float x0 = __expf(g0v - mx), x1 = __expf(g1v - mx);
  float x2 = __expf(g2v - mx), x3 = __expf(g3v - mx);
  float sx = x0 + x1 + x2 + x3;
  float A0 = x0 / sx, A1 = x1 / sx, A2 = x2 / sx, A3 = x3 / sx;

  // unbiased variance per archetype dim
  float m0 = sa0 / cnt, m1 = sa1 / cnt, m2 = sa2 / cnt, m3 = sa3 / cnt;
  float d1 = fmaxf(counts - 1.f, 1.f);
  float v0 = (q0 - counts * m0 * m0) / d1;
  float v1 = (q1 - counts * m1 * m1) / d1;
  float v2 = (q2 - counts * m2 * m2) / d1;
  float v3 = (q3 - counts * m3 * m3) / d1;
  float var_m = 0.25f * (v0 + v1 + v2 + v3);
  float phi_c = 1.f - fminf(1.f, var_m * 2.f);
  float coh   = 1.f - var_m;
  float pred  = ssur / cnt;
  float integ = phi_c * (1.f - pred);

  // cluster MLP: lane j owns hidden unit j (H/2 = 32)
  float cf6 = fminf(1.f, counts / 20.f);
  float h = c1[lane]
          + A0    * V1[lane]
          + A1    * V1[32  + lane]
          + A2    * V1[64  + lane]
          + A3    * V1[96  + lane]
          + phi_c * V1[128 + lane]
          + coh   * V1[160 + lane]
          + cf6   * V1[192 + lane];
  h = fmaxf(h, 0.f);
  float t = wsum(h * V2[lane]);
  float basec = 1.f / (1.f + __expf(-(t + c2[0])));
  float impc = fminf(fmaxf(basec * phi_c, 0.01f), 1.f);

  if (lane == 0) {
    float4* o = (float4*)(out + (size_t)wid * 8);
    o[0] = make_float4(A0, A1, A2, A3);
    o[1] = make_float4(phi_c, coh, pred, integ);
    g_impc[wid]   = impc;
    g_validf[wid] = valid ? 1.f : 0.f;
  }
}

// ---------------- K3: organism-level reduction (single block, deterministic) -
__global__ void k_final(float* __restrict__ out, int K) {
  __shared__ float red[8][8];
  __shared__ unsigned pres;
  int tid = threadIdx.x, lane = tid & 31, warp = tid >> 5;
  if (tid == 0) pres = 0u;
  __syncthreads();

  float ez = 0.f, g0 = 0.f, g1 = 0.f, g2 = 0.f, g3 = 0.f;
  float sp = 0.f, sc = 0.f, nv = 0.f;
  unsigned pl = 0u;
  for (int k = tid; k < K; k += 256) {
    if (g_validf[k] > 0.f) {
      const float* r = out + (size_t)k * 8;
      float a0 = r[0], a1 = r[1], a2 = r[2], a3 = r[3];
      float e = __expf(g_impc[k]);      // impc <= 1, shift-free softmax safe
      ez += e; g0 += e * a0; g1 += e * a1; g2 += e * a2; g3 += e * a3;
      sp += r[4]; sc += r[5]; nv += 1.f;
      int sm_ = 0; float bv = a0;
      if (a1 > bv) { bv = a1; sm_ = 1; }
      if (a2 > bv) { bv = a2; sm_ = 2; }
      if (a3 > bv) { bv = a3; sm_ = 3; }
      pl |= (1u << sm_);
    }
  }
  ez = wsum(ez); g0 = wsum(g0); g1 = wsum(g1); g2 = wsum(g2); g3 = wsum(g3);
  sp = wsum(sp); sc = wsum(sc); nv = wsum(nv);
  pl |= __shfl_xor_sync(FULL, pl, 16);
  pl |= __shfl_xor_sync(FULL, pl, 8);
  pl |= __shfl_xor_sync(FULL, pl, 4);
  pl |= __shfl_xor_sync(FULL, pl, 2);
  pl |= __shfl_xor_sync(FULL, pl, 1);
  if (lane == 0) {
    red[0][warp] = ez; red[1][warp] = g0; red[2][warp] = g1; red[3][warp] = g2;
    red[4][warp] = g3; red[5][warp] = sp; red[6][warp] = sc; red[7][warp] = nv;
    atomicOr(&pres, pl);   // bitwise -> order-independent
  }
  __syncthreads();
  if (tid == 0) {
    float t[8];
    #pragma unroll
    for (int q = 0; q < 8; q++) {
      float s_ = 0.f;
      #pragma unroll
      for (int w_ = 0; w_ < 8; w_++) s_ += red[q][w_];
      t[q] = s_;
    }
    float EZ = t[0];
    float G0 = t[1] / EZ, G1 = t[2] / EZ, G2 = t[3] / EZ, G3 = t[4] / EZ;
    float nval = fmaxf(t[7], 1.f);
    float avg_phi = t[5] / nval, vert = t[6] / nval;
    float mx = fmaxf(fmaxf(G0, G1), fmaxf(G2, G3));
    float x0 = __expf(G0 - mx), x1 = __expf(G1 - mx);
    float x2 = __expf(G2 - mx), x3 = __expf(G3 - mx);
    float sx = x0 + x1 + x2 + x3;
    float unique = (float)__popc(pres);
    float phig = fminf(1.f, avg_phi * (0.5f + 0.5f * unique / 4.f));
    float* o = out + (size_t)K * 8;
    o[0] = x0 / sx; o[1] = x1 / sx; o[2] = x2 / sx; o[3] = x3 / sx;
    o[4] = phig;    o[5] = vert;
  }
}

// ---------------- launch -----------------------------------------------------
extern "C" void kernel_launch(void* const* d_in, const int* in_sizes, int n_in,
                              void* d_out, int out_size) {
  const float* state    = (const float*)d_in[0];
  const float* arch     = (const float*)d_in[1];
  const float* energy   = (const float*)d_in[2];
  const float* phil     = (const float*)d_in[3];
  const float* surprise = (const float*)d_in[4];
  const int*   seg      = (const int*)  d_in[5];
  // d_in[6] = n_clusters (device scalar; K derived from out_size instead)
  const float* W1 = (const float*)d_in[7];
  const float* b1 = (const float*)d_in[8];
  const float* W2 = (const float*)d_in[9];
  const float* b2 = (const float*)d_in[10];
  const float* V1 = (const float*)d_in[11];
  const float* c1 = (const float*)d_in[12];
  const float* V2 = (const float*)d_in[13];
  const float* c2 = (const float*)d_in[14];

  int N = in_sizes[2];                 // energy: one element per cell
  int K = (out_size - 6) / 8;          // out = K*(A+4) + (A+2), A=4
  float* out = (float*)d_out;

  k_zero  <<<(K + 255) / 256, 256>>>(K);
  k_bounds<<<(N + 255) / 256, 256>>>(seg, N);
  k_cell  <<<(N + TILE - 1) / TILE, 256>>>(state, arch, energy, phil,
                                           W1, b1, W2, b2, N);
  k_cluster<<<(K * 32 + 255) / 256, 256>>>(arch, surprise, V1, c1, V2, c2,
                                           out, K);
  k_final <<<1, 256>>>(out, K);
}

// round 5
// speedup vs baseline: 1.0982x; 1.0982x over previous
#include <cuda_runtime.h>
#include <cuda_bf16.h>
#include <cstdint>
#include <cstddef>

#define FULL 0xffffffffu
#define TILE 128
#define FS 44   // feats shared stride in floats -> conflict-free A-fragment LDS

// ---------------- static device scratch (no allocations allowed) ------------
static __device__ float g_e[4194304];       // per-cell exp(w)
static __device__ int   g_starts[65536];
static __device__ int   g_ends[65536];
static __device__ float g_impc[65536];
static __device__ float g_validf[65536];

// ---------------- helpers ---------------------------------------------------
__device__ __forceinline__ uint32_t f2tf32(float f) {
  uint32_t u;
  asm("cvt.rna.tf32.f32 %0, %1;" : "=r"(u) : "f"(f));
  return u;
}

__device__ __forceinline__ float wsum(float v) {
  v += __shfl_xor_sync(FULL, v, 16);
  v += __shfl_xor_sync(FULL, v, 8);
  v += __shfl_xor_sync(FULL, v, 4);
  v += __shfl_xor_sync(FULL, v, 2);
  v += __shfl_xor_sync(FULL, v, 1);
  return v;
}

// ---------------- K0: zero segment boundary arrays ---------------------------
__global__ void k_zero(int K) {
  int i = blockIdx.x * blockDim.x + threadIdx.x;
  if (i < K) { g_starts[i] = 0; g_ends[i] = 0; }
}

// ---------------- K0b: segment boundaries (seg_ids sorted) -------------------
__global__ void k_bounds(const int* __restrict__ seg, int N) {
  int i = blockIdx.x * blockDim.x + threadIdx.x;
  if (i >= N) return;
  int cur = seg[i];
  if (i == 0) g_starts[cur] = 0;
  int nxt = (i + 1 < N) ? seg[i + 1] : -1;
  if (nxt != cur) {
    g_ends[cur] = i + 1;
    if (i + 1 < N) g_starts[nxt] = i + 1;
  }
}

// ---------------- K1: per-cell MLP (tf32 MMA) -> e = exp(w) ------------------
// Persistent CTAs, software-pipelined: while tile t's MMA runs from smem,
// tile t+1's global loads are in flight into registers. W1 staged once/CTA.
__global__ void __launch_bounds__(256) k_cell(
    const float* __restrict__ state, const float* __restrict__ arch,
    const float* __restrict__ energy, const float* __restrict__ phil,
    const float* __restrict__ W1, const float* __restrict__ b1,
    const float* __restrict__ W2, const float* __restrict__ b2,
    int N)
{
  __shared__ float  feats[TILE * FS];   // 22.0 KB
  __shared__ uint2  bfrag[1280];        // 10.0 KB  [kt][nt][lane] tf32 B frags
  __shared__ float2 w2b1[64];           // {b1[col], W2[col]}
  __shared__ float  basebuf[TILE];

  int tid = threadIdx.x;

  // ---- stage W1 once per CTA as m16n8k8 .row.col B fragments:
  // b.x = B[k0][n], b.y = B[k0+4][n], k0 = kt*8+(lane&3), n = nt*8+(lane>>2)
  #pragma unroll
  for (int it = 0; it < 5; it++) {
    int idx = tid + it * 256;
    int l = idx & 31, nt = (idx >> 5) & 7, kt = idx >> 8;
    int k0 = kt * 8 + (l & 3), n = nt * 8 + (l >> 2);
    float f0 = (k0     < 36) ? W1[k0 * 64 + n]       : 0.f;
    float f1 = (k0 + 4 < 36) ? W1[(k0 + 4) * 64 + n] : 0.f;
    bfrag[idx] = make_uint2(f2tf32(f0), f2tf32(f1));
  }
  if (tid < 64) w2b1[tid] = make_float2(b1[tid], W2[tid]);
  float B2 = *b2;

  const float4* st4 = (const float4*)state;
  const float4* ar4 = (const float4*)arch;
  float4 z4 = make_float4(0.f, 0.f, 0.f, 0.f);

  int warp = tid >> 5, lane = tid & 31;
  int grp = lane >> 2, tig = lane & 3;
  int r0 = warp * 16 + grp;
  int row_ld = tid >> 3, q_ld = tid & 7;   // 4 tiles of 32 rows per iteration

  int ntiles = (N + TILE - 1) / TILE;
  int t = blockIdx.x;

  // ---- prefetch tile t into registers
  float4 st_r[4]; float4 a_r = z4; float ene_r = 0.f, phi_r = 0.f;
  {
    int base = t * TILE;
    #pragma unroll
    for (int it = 0; it < 4; it++) {
      int cell = base + row_ld + it * 32;
      st_r[it] = (cell < N) ? st4[(size_t)cell * 8 + q_ld] : z4;
    }
    if (tid < TILE) {
      int cell = base + tid;
      if (cell < N) { a_r = ar4[cell]; ene_r = energy[cell]; phi_r = phil[cell]; }
    }
  }

  while (t < ntiles) {
    int base = t * TILE;
    // ---- [A] registers -> smem feats
    #pragma unroll
    for (int it = 0; it < 4; it++)
      *(float4*)&feats[(row_ld + it * 32) * FS + q_ld * 4] = st_r[it];
    if (tid < TILE) {
      *(float4*)&feats[tid * FS + 32] = a_r;
      *(float4*)&feats[tid * FS + 36] = z4;   // k-pad 36..39
    }
    __syncthreads();

    float ene_c = ene_r, phi_c = phi_r;

    // ---- [B1] issue next tile's loads (overlap with MMA below)
    int tn = t + gridDim.x;
    if (tn < ntiles) {
      int nb = tn * TILE;
      #pragma unroll
      for (int it = 0; it < 4; it++) {
        int cell = nb + row_ld + it * 32;
        st_r[it] = (cell < N) ? st4[(size_t)cell * 8 + q_ld] : z4;
      }
      if (tid < TILE) {
        int cell = nb + tid;
        a_r = z4; ene_r = 0.f; phi_r = 0.f;
        if (cell < N) { a_r = ar4[cell]; ene_r = energy[cell]; phi_r = phil[cell]; }
      }
    }

    // ---- [B2] 5 k-tiles x 8 n-tiles of mma.m16n8k8.tf32
    float acc[8][4];
    #pragma unroll
    for (int nt = 0; nt < 8; nt++) {
      acc[nt][0] = 0.f; acc[nt][1] = 0.f; acc[nt][2] = 0.f; acc[nt][3] = 0.f;
    }
    #pragma unroll
    for (int kt = 0; kt < 5; kt++) {
      const float* fp = &feats[r0 * FS + kt * 8 + tig];
      uint32_t a0 = f2tf32(fp[0]);
      uint32_t a1 = f2tf32(fp[8 * FS]);
      uint32_t a2 = f2tf32(fp[4]);
      uint32_t a3 = f2tf32(fp[8 * FS + 4]);
      #pragma unroll
      for (int nt = 0; nt < 8; nt++) {
        uint2 b = bfrag[kt * 256 + nt * 32 + lane];
        asm volatile(
          "mma.sync.aligned.m16n8k8.row.col.f32.tf32.tf32.f32 "
          "{%0,%1,%2,%3}, {%4,%5,%6,%7}, {%8,%9}, {%0,%1,%2,%3};"
          : "+f"(acc[nt][0]), "+f"(acc[nt][1]), "+f"(acc[nt][2]), "+f"(acc[nt][3])
          : "r"(a0), "r"(a1), "r"(a2), "r"(a3), "r"(b.x), "r"(b.y));
      }
    }

    // ---- [B3] epilogue: base = sigmoid(relu(h+b1).W2 + b2)
    // C frag: c0,c1 = row r0 cols {8nt+2tig, +1}; c2,c3 = row r0+8 same cols
    float p0 = 0.f, p1 = 0.f;
    #pragma unroll
    for (int nt = 0; nt < 8; nt++) {
      int col = nt * 8 + tig * 2;
      float2 u = w2b1[col], v = w2b1[col + 1];
      p0 += fmaxf(acc[nt][0] + u.x, 0.f) * u.y + fmaxf(acc[nt][1] + v.x, 0.f) * v.y;
      p1 += fmaxf(acc[nt][2] + u.x, 0.f) * u.y + fmaxf(acc[nt][3] + v.x, 0.f) * v.y;
    }
    p0 += __shfl_xor_sync(FULL, p0, 1);
    p0 += __shfl_xor_sync(FULL, p0, 2);
    p1 += __shfl_xor_sync(FULL, p1, 1);
    p1 += __shfl_xor_sync(FULL, p1, 2);
    if (tig == 0) {
      basebuf[r0]     = 1.f / (1.f + __expf(-(p0 + B2)));
      basebuf[r0 + 8] = 1.f / (1.f + __expf(-(p1 + B2)));
    }
    __syncthreads();

    // ---- [C] w = clip(base*e*p,.01,1)*e*p; store exp(w) (w in [0,1], shift-free)
    if (tid < TILE) {
      int cell = base + tid;
      if (cell < N) {
        float ep = ene_c * phi_c;
        float imp = fminf(fmaxf(basebuf[tid] * ep, 0.01f), 1.f);
        g_e[cell] = __expf(imp * ep);
      }
    }
    t = tn;
  }
}

// ---------------- K2: one warp per cluster — reductions + cluster MLP --------
__global__ void k_cluster(
    const float* __restrict__ arch, const float* __restrict__ surprise,
    const float* __restrict__ V1, const float* __restrict__ c1,
    const float* __restrict__ V2, const float* __restrict__ c2,
    float* __restrict__ out, int K)
{
  int wid  = (blockIdx.x * blockDim.x + threadIdx.x) >> 5;
  int lane = threadIdx.x & 31;
  if (wid >= K) return;
  int s = g_starts[wid], e = g_ends[wid];
  const float4* ar4 = (const float4*)arch;

  float se = 0.f;
  float ea0 = 0.f, ea1 = 0.f, ea2 = 0.f, ea3 = 0.f;
  float sa0 = 0.f, sa1 = 0.f, sa2 = 0.f, sa3 = 0.f;
  float q0 = 0.f, q1 = 0.f, q2 = 0.f, q3 = 0.f;
  float ssur = 0.f;
  for (int i = s + lane; i < e; i += 32) {
    float4 a = ar4[i];
    float ev = g_e[i];
    float sp = surprise[i];
    se += ev;
    ea0 += ev * a.x; ea1 += ev * a.y; ea2 += ev * a.z; ea3 += ev * a.w;
    sa0 += a.x;      sa1 += a.y;      sa2 += a.z;      sa3 += a.w;
    q0 += a.x * a.x; q1 += a.y * a.y; q2 += a.z * a.z; q3 += a.w * a.w;
    ssur += sp;
  }
  se  = wsum(se);
  ea0 = wsum(ea0); ea1 = wsum(ea1); ea2 = wsum(ea2); ea3 = wsum(ea3);
  sa0 = wsum(sa0); sa1 = wsum(sa1); sa2 = wsum(sa2); sa3 = wsum(sa3);
  q0  = wsum(q0);  q1  = wsum(q1);  q2  = wsum(q2);  q3  = wsum(q3);
  ssur = wsum(ssur);

  int icnt = e - s;
  float counts = (float)icnt;
  bool  valid = icnt > 0;
  float cnt = fmaxf(counts, 1.f);

  // aggregate = softmax(segsum(wn*arch)); segsum(wn*arch) == ea/se (shift-free)
  float g0v = valid ? ea0 / se : 0.f;
  float g1v = valid ? ea1 / se : 0.f;
  float g2v = valid ? ea2 / se : 0.f;
  float g3v = valid ? ea3 / se : 0.f;
  float mx = fmaxf(fmaxf(g0v, g1v), fmaxf(g2v, g3v));
  float x0 = __expf(g0v - mx), x1 = __expf(g1v - mx);
  float x2 = __expf(g2v - mx), x3 = __expf(g3v - mx);
  float sx = x0 + x1 + x2 + x3;
  float A0 = x0 / sx, A1 = x1 / sx, A2 = x2 / sx, A3 = x3 / sx;

  // unbiased variance per archetype dim
  float m0 = sa0 / cnt, m1 = sa1 / cnt, m2 = sa2 / cnt, m3 = sa3 / cnt;
  float d1 = fmaxf(counts - 1.f, 1.f);
  float v0 = (q0 - counts * m0 * m0) / d1;
  float v1 = (q1 - counts * m1 * m1) / d1;
  float v2 = (q2 - counts * m2 * m2) / d1;
  float v3 = (q3 - counts * m3 * m3) / d1;
  float var_m = 0.25f * (v0 + v1 + v2 + v3);
  float phi_c = 1.f - fminf(1.f, var_m * 2.f);
  float coh   = 1.f - var_m;
  float pred  = ssur / cnt;
  float integ = phi_c * (1.f - pred);

  // cluster MLP: lane j owns hidden unit j (H/2 = 32)
  float cf6 = fminf(1.f, counts / 20.f);
  float h = c1[lane]
          + A0    * V1[lane]
          + A1    * V1[32  + lane]
          + A2    * V1[64  + lane]
          + A3    * V1[96  + lane]
          + phi_c * V1[128 + lane]
          + coh   * V1[160 + lane]
          + cf6   * V1[192 + lane];
  h = fmaxf(h, 0.f);
  float t = wsum(h * V2[lane]);
  float basec = 1.f / (1.f + __expf(-(t + c2[0])));
  float impc = fminf(fmaxf(basec * phi_c, 0.01f), 1.f);

  if (lane == 0) {
    float4* o = (float4*)(out + (size_t)wid * 8);
    o[0] = make_float4(A0, A1, A2, A3);
    o[1] = make_float4(phi_c, coh, pred, integ);
    g_impc[wid]   = impc;
    g_validf[wid] = valid ? 1.f : 0.f;
  }
}

// ---------------- K3: organism-level reduction (single block, deterministic) -
__global__ void k_final(float* __restrict__ out, int K) {
  __shared__ float red[8][8];
  __shared__ unsigned pres;
  int tid = threadIdx.x, lane = tid & 31, warp = tid >> 5;
  if (tid == 0) pres = 0u;
  __syncthreads();

  float ez = 0.f, g0 = 0.f, g1 = 0.f, g2 = 0.f, g3 = 0.f;
  float sp = 0.f, sc = 0.f, nv = 0.f;
  unsigned pl = 0u;
  for (int k = tid; k < K; k += 256) {
    if (g_validf[k] > 0.f) {
      const float* r = out + (size_t)k * 8;
      float a0 = r[0], a1 = r[1], a2 = r[2], a3 = r[3];
      float e = __expf(g_impc[k]);      // impc <= 1, shift-free softmax safe
      ez += e; g0 += e * a0; g1 += e * a1; g2 += e * a2; g3 += e * a3;
      sp += r[4]; sc += r[5]; nv += 1.f;
      int sm_ = 0; float bv = a0;
      if (a1 > bv) { bv = a1; sm_ = 1; }
      if (a2 > bv) { bv = a2; sm_ = 2; }
      if (a3 > bv) { bv = a3; sm_ = 3; }
      pl |= (1u << sm_);
    }
  }
  ez = wsum(ez); g0 = wsum(g0); g1 = wsum(g1); g2 = wsum(g2); g3 = wsum(g3);
  sp = wsum(sp); sc = wsum(sc); nv = wsum(nv);
  pl |= __shfl_xor_sync(FULL, pl, 16);
  pl |= __shfl_xor_sync(FULL, pl, 8);
  pl |= __shfl_xor_sync(FULL, pl, 4);
  pl |= __shfl_xor_sync(FULL, pl, 2);
  pl |= __shfl_xor_sync(FULL, pl, 1);
  if (lane == 0) {
    red[0][warp] = ez; red[1][warp] = g0; red[2][warp] = g1; red[3][warp] = g2;
    red[4][warp] = g3; red[5][warp] = sp; red[6][warp] = sc; red[7][warp] = nv;
    atomicOr(&pres, pl);   // bitwise -> order-independent
  }
  __syncthreads();
  if (tid == 0) {
    float t[8];
    #pragma unroll
    for (int q = 0; q < 8; q++) {
      float s_ = 0.f;
      #pragma unroll
      for (int w_ = 0; w_ < 8; w_++) s_ += red[q][w_];
      t[q] = s_;
    }
    float EZ = t[0];
    float G0 = t[1] / EZ, G1 = t[2] / EZ, G2 = t[3] / EZ, G3 = t[4] / EZ;
    float nval = fmaxf(t[7], 1.f);
    float avg_phi = t[5] / nval, vert = t[6] / nval;
    float mx = fmaxf(fmaxf(G0, G1), fmaxf(G2, G3));
    float x0 = __expf(G0 - mx), x1 = __expf(G1 - mx);
    float x2 = __expf(G2 - mx), x3 = __expf(G3 - mx);
    float sx = x0 + x1 + x2 + x3;
    float unique = (float)__popc(pres);
    float phig = fminf(1.f, avg_phi * (0.5f + 0.5f * unique / 4.f));
    float* o = out + (size_t)K * 8;
    o[0] = x0 / sx; o[1] = x1 / sx; o[2] = x2 / sx; o[3] = x3 / sx;
    o[4] = phig;    o[5] = vert;
  }
}

// ---------------- launch -----------------------------------------------------
extern "C" void kernel_launch(void* const* d_in, const int* in_sizes, int n_in,
                              void* d_out, int out_size) {
  const float* state    = (const float*)d_in[0];
  const float* arch     = (const float*)d_in[1];
  const float* energy   = (const float*)d_in[2];
  const float* phil     = (const float*)d_in[3];
  const float* surprise = (const float*)d_in[4];
  const int*   seg      = (const int*)  d_in[5];
  // d_in[6] = n_clusters (device scalar; K derived from out_size instead)
  const float* W1 = (const float*)d_in[7];
  const float* b1 = (const float*)d_in[8];
  const float* W2 = (const float*)d_in[9];
  const float* b2 = (const float*)d_in[10];
  const float* V1 = (const float*)d_in[11];
  const float* c1 = (const float*)d_in[12];
  const float* V2 = (const float*)d_in[13];
  const float* c2 = (const float*)d_in[14];

  int N = in_sizes[2];                 // energy: one element per cell
  int K = (out_size - 6) / 8;          // out = K*(A+4) + (A+2), A=4
  float* out = (float*)d_out;

  int ntiles = (N + TILE - 1) / TILE;
  int grid = 148 * 6;                  // persistent-style; strided tile loop
  if (grid > ntiles) grid = ntiles;

  k_zero  <<<(K + 255) / 256, 256>>>(K);
  k_bounds<<<(N + 255) / 256, 256>>>(seg, N);
  k_cell  <<<grid, 256>>>(state, arch, energy, phil, W1, b1, W2, b2, N);
  k_cluster<<<(K * 32 + 255) / 256, 256>>>(arch, surprise, V1, c1, V2, c2,
                                           out, K);
  k_final <<<1, 256>>>(out, K);
}